// round 4
// baseline (speedup 1.0000x reference)
#include <cuda_runtime.h>

// FP_14396730376440 — fan-beam forward projection, geometry recomputed on-GPU.
// Replaces the 408 MB grid_pos/weighting streams with an in-kernel Siddon-style
// merge of the two affine crossing sequences ax_k=(k+cx)/Dx, ay_k=(k+cy)/Dy.

#define ND 368
#define NV 180
#define NS 513
#define NRAYS (ND * NV)
#define IMG_W 256
#define IMG_H 256
#define PAD 2
#define PW (IMG_W + 2 * PAD)     // 260
#define NCHUNK 4
#define F_INF __int_as_float(0x7f800000)

// ---------------- static device scratch (no allocs allowed) ----------------
__device__ double d_cb[NV], d_sb[NV];
__device__ float2 d_img_pair[PW * PW];
__device__ float4 d_rayA[NRAYS];   // invDx, invDy, cx, cy
__device__ float4 d_rayB[NRAYS];   // fDx, fsx, fDy, fsy   (sample-pos affine)
__device__ float4 d_rayC[NRAYS];   // lo, hi, Dxf, Dyf
__device__ float  d_rayS[NRAYS];   // s2d

// ---------------- K1: per-view trig table (f64) ----------------
__global__ void trig_kernel()
{
    int v = threadIdx.x;
    if (v < NV) {
        double beta = (double)v * (3.14159265358979323846 * 2.0 / 180.0);
        d_cb[v] = cos(beta);
        d_sb[v] = sin(beta);
    }
}

// ---------------- K2: pair-packed zero-padded image ----------------
__global__ void pad_img_kernel(const float* __restrict__ img)
{
    int idx = blockIdx.x * blockDim.x + threadIdx.x;
    if (idx >= PW * PW) return;
    int y = idx / PW, x = idx % PW;
    int iy = y - PAD;
    auto px = [&](int xx) -> float {
        int ix = xx - PAD;
        if ((unsigned)ix < (unsigned)IMG_W && (unsigned)iy < (unsigned)IMG_H)
            return img[iy * IMG_W + ix];
        return 0.0f;
    };
    d_img_pair[idx] = make_float2(px(x), px(x + 1));
}

// ---------------- K3: per-ray geometry setup (f64 -> f32) ----------------
__global__ void ray_setup_kernel()
{
    int q = blockIdx.x * blockDim.x + threadIdx.x;
    if (q >= NRAYS) return;
    // q = v*ND + d : consecutive q = consecutive detectors of one view
    int v = q / ND;
    int d = q - v * ND;

    double cb = d_cb[v], sb = d_sb[v];
    double rdy = 2.0 * d - 367.0;                  // (d - 183.5) * 2
    double sx = -500.0 * cb, sy = 500.0 * sb;
    double detx = cb * 500.0 + sb * rdy;
    double dety = -sb * 500.0 + cb * rdy;
    double Dx = detx - sx, Dy = dety - sy;
    double cx = -128.0 - sx, cy = -128.0 - sy;
    double invDx = 1.0 / Dx, invDy = 1.0 / Dy;
    double s2d = sqrt(Dx * Dx + Dy * Dy);
    const double scale = 128.0 / 127.5;

    float invDxf = (float)invDx, invDyf = (float)invDy;
    float cxf = (float)cx, cyf = (float)cy;

    // Window endpoints in the SAME f32 arithmetic as the merge loop, so the
    // defining endpoint crossings compare exactly against lo/hi.
    float ex0 = (0.0f   + cxf) * invDxf;
    float ex1 = (256.0f + cxf) * invDxf;
    float ey0 = (0.0f   + cyf) * invDyf;
    float ey1 = (256.0f + cyf) * invDyf;
    float lo = fmaxf(fmaxf(fminf(ex0, ex1), fminf(ey0, ey1)), 0.0f);
    float hi = fminf(fminf(fmaxf(ex0, ex1), fmaxf(ey0, ey1)), 1.0f);

    d_rayA[q] = make_float4(invDxf, invDyf, cxf, cyf);
    d_rayB[q] = make_float4((float)(Dx * scale), (float)(sx * scale + 127.5),
                            (float)(Dy * scale), (float)(sy * scale + 127.5));
    d_rayC[q] = make_float4(lo, hi, (float)Dx, (float)Dy);
    d_rayS[q] = (float)s2d;
}

// crossing value during forward merge: +INF once index leaves [0,256]
__device__ __forceinline__ float cval_fwd(float kf, float cf, float inv)
{
    return (fabsf(kf - 128.0f) <= 128.5f) ? (kf + cf) * inv : F_INF;
}

// crossing value for init: out-of-range acts as -INF on the "before first"
// side of the ascending enumeration and +INF past the end
__device__ __forceinline__ float cval_init(float kf, float cf, float inv, float dirf)
{
    if (kf < -0.5f)  return dirf > 0.0f ? -F_INF : F_INF;
    if (kf > 256.5f) return dirf > 0.0f ? F_INF : -F_INF;
    return (kf + cf) * inv;
}

// find first crossing (ascending) with value >= clo
__device__ __forceinline__ void init_family(float clo, float Df, float cf,
                                            float inv, float dirf,
                                            float& kf, float& v)
{
    float t = fmaf(clo, Df, -cf);                  // ideal real-valued index
    kf = fminf(fmaxf(rintf(t), -1.0f), 257.0f);
    #pragma unroll 1
    for (int i = 0; i < 16; ++i) {
        float vc = cval_init(kf, cf, inv, dirf);
        float vp = cval_init(kf - dirf, cf, inv, dirf);
        if (vc < clo)       kf += dirf;
        else if (vp >= clo) kf -= dirf;
        else break;
    }
    v = cval_fwd(kf, cf, inv);
}

// ---------------- K4: main kernel, 4 chunk-threads per ray ----------------
__global__ __launch_bounds__(256)
void fp_kernel(float* __restrict__ out)
{
    const int g = blockIdx.x * blockDim.x + threadIdx.x;
    if (g >= NRAYS * NCHUNK) return;
    const int q = g >> 2;
    const int chunk = g & 3;

    const float4 A = d_rayA[q];
    const float4 B = d_rayB[q];
    const float4 C = d_rayC[q];
    const float invDx = A.x, invDy = A.y, cx = A.z, cy = A.w;
    const float fDx = B.x, fsx = B.y, fDy = B.z, fsy = B.w;
    const float lo = C.x, hi = C.y, Dxf = C.z, Dyf = C.w;
    const float dirx = (invDx > 0.0f) ? 1.0f : -1.0f;
    const float diry = (invDy > 0.0f) ? 1.0f : -1.0f;

    // chunk owns crossings in [clo, chi) (chunk 3: [clo, hi], via next>hi break)
    const float w4 = (hi - lo) * 0.25f;
    const float clo = fmaf((float)chunk, w4, lo);
    const float limit = (chunk == 3) ? F_INF : fmaf((float)(chunk + 1), w4, lo);

    float kxf, vx, kyf, vy;
    init_family(clo, Dxf, cx, invDx, dirx, kxf, vx);
    init_family(clo, Dyf, cy, invDy, diry, kyf, vy);

    float acc = 0.0f;
    float cprev = fminf(vx, vy);
    // advance the family that produced cprev
    if (vx <= vy) { kxf += dirx; vx = cval_fwd(kxf, cx, invDx); }
    else          { kyf += diry; vy = cval_fwd(kyf, cy, invDy); }

    const float2* __restrict__ ip = d_img_pair + (PAD * PW + PAD);

    #pragma unroll 1
    while (cprev < limit) {
        const float nxt = fminf(vx, vy);
        if (nxt > hi) break;

        const float w   = nxt - cprev;
        const float mid = fmaf(0.5f, w, cprev);
        const float ix  = fmaf(mid, fDx, fsx);
        const float iy  = fmaf(mid, fDy, fsy);
        const float x0f = floorf(ix);
        const float y0f = floorf(iy);
        const float fx  = ix - x0f;
        const float fy  = iy - y0f;
        const int idx   = __float2int_rn(y0f) * PW + __float2int_rn(x0f);

        const float2 t0 = __ldg(ip + idx);
        const float2 t1 = __ldg(ip + idx + PW);
        const float top = fmaf(fx, t0.y - t0.x, t0.x);
        const float bot = fmaf(fx, t1.y - t1.x, t1.x);
        const float f   = fmaf(fy, bot - top, top);
        acc = fmaf(w, f, acc);

        if (vx <= vy) { kxf += dirx; vx = cval_fwd(kxf, cx, invDx); }
        else          { kyf += diry; vy = cval_fwd(kyf, cy, invDy); }
        cprev = nxt;
    }

    // combine the 4 chunk partials (threads 4r..4r+3 are in one warp)
    acc += __shfl_xor_sync(0xffffffffu, acc, 1);
    acc += __shfl_xor_sync(0xffffffffu, acc, 2);

    if (chunk == 0) {
        const int v = q / ND;
        const int d = q - v * ND;
        out[d * NV + v] = d_rayS[q] * acc;
    }
}

extern "C" void kernel_launch(void* const* d_in, const int* in_sizes, int n_in,
                              void* d_out, int out_size)
{
    const float* img = (const float*)d_in[0];
    float* out = (float*)d_out;

    trig_kernel<<<1, 192>>>();
    pad_img_kernel<<<(PW * PW + 255) / 256, 256>>>(img);
    ray_setup_kernel<<<(NRAYS + 255) / 256, 256>>>();
    fp_kernel<<<(NRAYS * NCHUNK + 255) / 256, 256>>>(out);
}

// round 5
// speedup vs baseline: 1.2972x; 1.2972x over previous
#include <cuda_runtime.h>

// FP_14396730376440 — fan-beam forward projection, geometry recomputed on-GPU.
// Zero-DRAM-stream: in-kernel merge of two affine crossing sequences
// cval(k) = fmaf(k, inv, off) per family; branch-free advance, no range checks
// (values are monotone past the endpoints, so the nxt > hi break handles it).

#define ND 368
#define NV 180
#define NRAYS (ND * NV)
#define IMG_W 256
#define IMG_H 256
#define PAD 2
#define PW (IMG_W + 2 * PAD)     // 260
#define NCHUNK 8
#define F_INF __int_as_float(0x7f800000)

// ---------------- static device scratch ----------------
__device__ float2 d_img_pair[PW * PW];
__device__ float4 d_rayA[NRAYS];   // invx, offx, invy, offy
__device__ float4 d_rayB[NRAYS];   // fDx, fsx, fDy, fsy   (sample-pos affine)
__device__ float4 d_rayC[NRAYS];   // lo, hi, Dx, Dy
__device__ float  d_rayS[NRAYS];   // s2d

#define PAD_BLOCKS ((PW * PW + 255) / 256)
#define RAY_BLOCKS ((NRAYS + 255) / 256)

// ---------------- K1: fused pad + per-ray setup (pure f32) ----------------
__global__ void setup_kernel(const float* __restrict__ img)
{
    if (blockIdx.x < PAD_BLOCKS) {
        int idx = blockIdx.x * 256 + threadIdx.x;
        if (idx >= PW * PW) return;
        int y = idx / PW, x = idx % PW;
        int iy = y - PAD;
        auto px = [&](int xx) -> float {
            int ix = xx - PAD;
            if ((unsigned)ix < (unsigned)IMG_W && (unsigned)iy < (unsigned)IMG_H)
                return img[iy * IMG_W + ix];
            return 0.0f;
        };
        d_img_pair[idx] = make_float2(px(x), px(x + 1));
        return;
    }

    int q = (blockIdx.x - PAD_BLOCKS) * 256 + threadIdx.x;
    if (q >= NRAYS) return;
    int v = q / ND;
    int d = q - v * ND;

    float sb, cb;
    sincospif((float)v / 90.0f, &sb, &cb);        // beta = v * 2*pi/180
    float rdy = 2.0f * (float)d - 367.0f;
    float sx = -500.0f * cb, sy = 500.0f * sb;
    float Dx = fmaf(sb, rdy, 500.0f * cb) - sx;
    float Dy = fmaf(cb, rdy, -500.0f * sb) - sy;
    float cx = -128.0f - sx, cy = -128.0f - sy;
    float invx = 1.0f / Dx, invy = 1.0f / Dy;
    float offx = cx * invx, offy = cy * invy;

    // Window endpoints in the SAME fmaf form the merge loop uses.
    float ex0 = offx, ex1 = fmaf(256.0f, invx, offx);
    float ey0 = offy, ey1 = fmaf(256.0f, invy, offy);
    float lo = fmaxf(fmaxf(fminf(ex0, ex1), fminf(ey0, ey1)), 0.0f);
    float hi = fminf(fminf(fmaxf(ex0, ex1), fmaxf(ey0, ey1)), 1.0f);

    const float scale = 128.0f / 127.5f;
    d_rayA[q] = make_float4(invx, offx, invy, offy);
    d_rayB[q] = make_float4(Dx * scale, fmaf(sx, scale, 127.5f),
                            Dy * scale, fmaf(sy, scale, 127.5f));
    d_rayC[q] = make_float4(lo, hi, Dx, Dy);
    d_rayS[q] = sqrtf(fmaf(Dx, Dx, Dy * Dy));
}

// find first crossing (ascending order) with value >= clo
__device__ __forceinline__ void init_family(float clo, float Df, float inv,
                                            float off, float dirf,
                                            float& kf, float& val)
{
    float k = rintf((clo - off) * Df);
    k = fminf(fmaxf(k, -2.0f), 258.0f);
    #pragma unroll
    for (int i = 0; i < 4; ++i) {
        float vc = fmaf(k, inv, off);
        if (vc < clo)                                k += dirf;
        else if (fmaf(k - dirf, inv, off) >= clo)    k -= dirf;
        else break;
    }
    kf = k;
    val = fmaf(k, inv, off);
}

// ---------------- K2: main kernel, 8 chunk-threads per ray ----------------
__global__ __launch_bounds__(256)
void fp_kernel(float* __restrict__ out)
{
    const int g = blockIdx.x * blockDim.x + threadIdx.x;
    if (g >= NRAYS * NCHUNK) return;
    const int q = g >> 3;
    const int chunk = g & 7;

    const float4 A = d_rayA[q];
    const float4 B = d_rayB[q];
    const float4 C = d_rayC[q];
    const float invx = A.x, offx = A.y, invy = A.z, offy = A.w;
    const float fDx = B.x, fsx = B.y, fDy = B.z, fsy = B.w;
    const float lo = C.x, hi = C.y, Dx = C.z, Dy = C.w;
    const float dirx = (invx > 0.0f) ? 1.0f : -1.0f;
    const float diry = (invy > 0.0f) ? 1.0f : -1.0f;

    // chunk owns intervals starting in [clo, limit)
    const float w8 = (hi - lo) * 0.125f;
    const float clo = fmaf((float)chunk, w8, lo);
    const float limit = (chunk == 7) ? F_INF : fmaf((float)(chunk + 1), w8, lo);

    float kx, vx, ky, vy;
    init_family(clo, Dx, invx, offx, dirx, kx, vx);
    init_family(clo, Dy, invy, offy, diry, ky, vy);

    float acc = 0.0f;
    float cprev = fminf(vx, vy);
    if (vx <= vy) { kx += dirx; vx = fmaf(kx, invx, offx); }
    else          { ky += diry; vy = fmaf(ky, invy, offy); }

    const float2* __restrict__ ip = d_img_pair + (PAD * PW + PAD);

    #pragma unroll 1
    while (cprev < limit) {
        const float nxt = fminf(vx, vy);
        if (nxt > hi) break;

        const float w   = nxt - cprev;
        const float mid = fmaf(0.5f, w, cprev);
        const float ix  = fmaf(mid, fDx, fsx);
        const float iy  = fmaf(mid, fDy, fsy);
        const float x0f = floorf(ix);
        const float y0f = floorf(iy);
        const float fx  = ix - x0f;
        const float fy  = iy - y0f;
        const int idx   = __float2int_rn(y0f) * PW + __float2int_rn(x0f);

        const float2 t0 = __ldg(ip + idx);
        const float2 t1 = __ldg(ip + idx + PW);
        const float top = fmaf(fx, t0.y - t0.x, t0.x);
        const float bot = fmaf(fx, t1.y - t1.x, t1.x);
        acc = fmaf(w, fmaf(fy, bot - top, top), acc);

        if (vx <= vy) { kx += dirx; vx = fmaf(kx, invx, offx); }
        else          { ky += diry; vy = fmaf(ky, invy, offy); }
        cprev = nxt;
    }

    // combine the 8 chunk partials (threads 8r..8r+7 share a warp)
    acc += __shfl_xor_sync(0xffffffffu, acc, 1);
    acc += __shfl_xor_sync(0xffffffffu, acc, 2);
    acc += __shfl_xor_sync(0xffffffffu, acc, 4);

    if (chunk == 0) {
        const int v = q / ND;
        const int d = q - v * ND;
        out[d * NV + v] = d_rayS[q] * acc;
    }
}

extern "C" void kernel_launch(void* const* d_in, const int* in_sizes, int n_in,
                              void* d_out, int out_size)
{
    const float* img = (const float*)d_in[0];
    float* out = (float*)d_out;

    setup_kernel<<<PAD_BLOCKS + RAY_BLOCKS, 256>>>(img);
    fp_kernel<<<(NRAYS * NCHUNK + 255) / 256, 256>>>(out);
}